// round 4
// baseline (speedup 1.0000x reference)
#include <cuda_runtime.h>
#include <cuda_fp16.h>

// ---------------------------------------------------------------------------
// SSIM3D: two fp32 volumes (4,1,160,160,160), 11-tap separable Gaussian,
// 5 statistics (mu1, mu2, E11, E22, E12), scalar mean output.
//
// Pass A: one block per (z,b). 160 threads own one full x-row. Slide along y
//   with 11-slot circular register accumulators (scatter-accumulate):
//   x-conv computed once per input row; y-conv built incrementally.
//   Prologue rows 0..4 guard out-of-range outputs (the R3 bug).
//   Writes 5-channel fp16 intermediate. Zero read amplification.
// Pass B: one block per (y,b). Slide along z the same way (no smem, no
//   syncs), read the intermediate exactly once, SSIM map with an FMA-only
//   Newton reciprocal (no MUFU), block-reduce into a double.
// ---------------------------------------------------------------------------

namespace {
constexpr int D    = 160;
constexpr int DD   = D * D;                 // 25600
constexpr int NB   = 4;
constexpr long long VOL  = (long long)D * DD;       // 4,096,000
constexpr long long NIMG = (long long)NB * VOL;     // 16,384,000
constexpr float C1 = 0.0001f;   // 0.01^2
constexpr float C2 = 0.0009f;   // 0.03^2
}

// Normalized Gaussian, sigma=1.5, 11 taps.
__device__ constexpr float W[11] = {
    0.00102838f, 0.00759876f, 0.03600077f, 0.10936070f, 0.21300554f,
    0.26601173f,
    0.21300554f, 0.10936070f, 0.03600077f, 0.00759876f, 0.00102838f};

// 5 channels x 4 batches x 160^3 halfs = 163.84 MB scratch.
__device__ __half g_mid[5ll * 16384000ll];
__device__ double g_sum;

// Pure-FMA reciprocal (den is positive, >= ~9e-8); 3 Newton steps -> ~1ulp.
__device__ __forceinline__ float frcp(float x) {
    float r = __int_as_float(0x7EF311C3 - __float_as_int(x));
    r = r * (2.0f - x * r);
    r = r * (2.0f - x * r);
    r = r * (2.0f - x * r);
    return r;
}

// ---------------------------------------------------------------------------
// Pass A: x-conv + incremental y-conv, sliding along y.
// grid = (160 z, 4 b), block = 160 threads (one x column each).
// ---------------------------------------------------------------------------
__global__ void __launch_bounds__(160) pass_a(const float* __restrict__ img1,
                                              const float* __restrict__ img2) {
    __shared__ float sA[2][176];   // row double-buffer, 5-halo zeros at ends
    __shared__ float sC[2][176];

    const int z = blockIdx.x;
    const int b = blockIdx.y;
    const int x = threadIdx.x;

    const float* p1 = img1 + (long long)b * VOL + (long long)z * DD;
    const float* p2 = img2 + (long long)b * VOL + (long long)z * DD;

    // Zero both buffers once (halo stays zero forever).
    for (int i = x; i < 2 * 176; i += 160) {
        sA[i / 176][i % 176] = 0.f;
        sC[i / 176][i % 176] = 0.f;
    }

    float am1[11], am2[11], ae11[11], ae22[11], ae12[11];
#pragma unroll
    for (int i = 0; i < 11; i++) {
        am1[i] = am2[i] = ae11[i] = ae22[i] = ae12[i] = 0.f;
    }
    __syncthreads();

    const long long cs = (long long)NB * VOL;    // channel stride in g_mid
    __half* outp = g_mid + (long long)b * VOL + (long long)z * DD + x;

    // ---- Prologue: input rows y = 0..4 (outputs o = y-5+d must be >= 0) ----
#pragma unroll
    for (int y = 0; y < 5; y++) {
        const int buf = y & 1;
        sA[buf][5 + x] = p1[y * D + x];
        sC[buf][5 + x] = p2[y * D + x];
        __syncthreads();

        float fm1 = 0.f, fm2 = 0.f, fe11 = 0.f, fe22 = 0.f, fe12 = 0.f;
#pragma unroll
        for (int k = 0; k < 11; k++) {
            const float av = sA[buf][x + k];
            const float cv = sC[buf][x + k];
            const float wa = W[k] * av;
            const float wc = W[k] * cv;
            fm1  = fmaf(W[k], av, fm1);
            fm2  = fmaf(W[k], cv, fm2);
            fe11 = fmaf(wa, av, fe11);
            fe22 = fmaf(wc, cv, fe22);
            fe12 = fmaf(wa, cv, fe12);
        }
#pragma unroll
        for (int d = 0; d < 11; d++) {
            if (d >= 5 - y) {                      // only real outputs o >= 0
                const int sl = (y - 5 + d + 11) % 11;   // compile-time
                am1[sl]  = fmaf(W[10 - d], fm1,  am1[sl]);
                am2[sl]  = fmaf(W[10 - d], fm2,  am2[sl]);
                ae11[sl] = fmaf(W[10 - d], fe11, ae11[sl]);
                ae22[sl] = fmaf(W[10 - d], fe22, ae22[sl]);
                ae12[sl] = fmaf(W[10 - d], fe12, ae12[sl]);
            }
        }
    }

    // ---- Steady state: input rows y = 5..169, emit output o = y-5 ----
    for (int yb = 0; yb < 165; yb += 11) {
#pragma unroll
        for (int s = 0; s < 11; s++) {
            const int y = 5 + yb + s;
            const int buf = y & 1;

            float a = 0.f, c = 0.f;
            if (y < D) {
                a = p1[y * D + x];
                c = p2[y * D + x];
            }
            sA[buf][5 + x] = a;
            sC[buf][5 + x] = c;
            __syncthreads();

            float fm1 = 0.f, fm2 = 0.f, fe11 = 0.f, fe22 = 0.f, fe12 = 0.f;
#pragma unroll
            for (int k = 0; k < 11; k++) {
                const float av = sA[buf][x + k];
                const float cv = sC[buf][x + k];
                const float wa = W[k] * av;
                const float wc = W[k] * cv;
                fm1  = fmaf(W[k], av, fm1);
                fm2  = fmaf(W[k], cv, fm2);
                fe11 = fmaf(wa, av, fe11);
                fe22 = fmaf(wc, cv, fe22);
                fe12 = fmaf(wa, cv, fe12);
            }

            // Output o = y-5+d -> slot (yb+s+d) mod 11 = (s+d) mod 11.
#pragma unroll
            for (int d = 0; d < 11; d++) {
                const int sl = (s + d) % 11;       // compile-time
                am1[sl]  = fmaf(W[10 - d], fm1,  am1[sl]);
                am2[sl]  = fmaf(W[10 - d], fm2,  am2[sl]);
                ae11[sl] = fmaf(W[10 - d], fe11, ae11[sl]);
                ae22[sl] = fmaf(W[10 - d], fe22, ae22[sl]);
                ae12[sl] = fmaf(W[10 - d], fe12, ae12[sl]);
            }

            // Output row o = y-5 complete; slot (o mod 11) = s.
            const int o = yb + s;
            if (o < D) {
                __half* q = outp + (long long)o * D;
                q[0]      = __float2half_rn(am1[s]);
                q[cs]     = __float2half_rn(am2[s]);
                q[2 * cs] = __float2half_rn(ae11[s]);
                q[3 * cs] = __float2half_rn(ae22[s]);
                q[4 * cs] = __float2half_rn(ae12[s]);
            }
            am1[s] = am2[s] = ae11[s] = ae22[s] = ae12[s] = 0.f;
        }
    }
}

// ---------------------------------------------------------------------------
// Pass B: z-conv sliding along z + SSIM map + reduction. No smem tiles.
// grid = (160 y, 4 b), block = 160 threads (one x column each).
// ---------------------------------------------------------------------------
__global__ void __launch_bounds__(160) pass_b() {
    __shared__ float red[5];

    const int y = blockIdx.x;
    const int b = blockIdx.y;
    const int x = threadIdx.x;
    const int tid = threadIdx.x;

    const long long cs = (long long)NB * VOL;
    const __half* base = g_mid + (long long)b * VOL + (long long)y * D + x;

    float am1[11], am2[11], ae11[11], ae22[11], ae12[11];
#pragma unroll
    for (int i = 0; i < 11; i++) {
        am1[i] = am2[i] = ae11[i] = ae22[i] = ae12[i] = 0.f;
    }

    float lsum = 0.f;

    // ---- Prologue: z = 0..4 (guard out-of-range outputs) ----
#pragma unroll
    for (int z = 0; z < 5; z++) {
        const __half* p = base + (long long)z * DD;
        const float f0 = __half2float(p[0]);
        const float f1 = __half2float(p[cs]);
        const float f2 = __half2float(p[2 * cs]);
        const float f3 = __half2float(p[3 * cs]);
        const float f4 = __half2float(p[4 * cs]);
#pragma unroll
        for (int d = 0; d < 11; d++) {
            if (d >= 5 - z) {
                const int sl = (z - 5 + d + 11) % 11;
                am1[sl]  = fmaf(W[10 - d], f0, am1[sl]);
                am2[sl]  = fmaf(W[10 - d], f1, am2[sl]);
                ae11[sl] = fmaf(W[10 - d], f2, ae11[sl]);
                ae22[sl] = fmaf(W[10 - d], f3, ae22[sl]);
                ae12[sl] = fmaf(W[10 - d], f4, ae12[sl]);
            }
        }
    }

    // ---- Steady state: z = 5..169, emit output o = z-5 ----
    for (int zb = 0; zb < 165; zb += 11) {
#pragma unroll
        for (int s = 0; s < 11; s++) {
            const int z = 5 + zb + s;

            float f0 = 0.f, f1 = 0.f, f2 = 0.f, f3 = 0.f, f4 = 0.f;
            if (z < D) {
                const __half* p = base + (long long)z * DD;
                f0 = __half2float(p[0]);
                f1 = __half2float(p[cs]);
                f2 = __half2float(p[2 * cs]);
                f3 = __half2float(p[3 * cs]);
                f4 = __half2float(p[4 * cs]);
            }

#pragma unroll
            for (int d = 0; d < 11; d++) {
                const int sl = (s + d) % 11;
                am1[sl]  = fmaf(W[10 - d], f0, am1[sl]);
                am2[sl]  = fmaf(W[10 - d], f1, am2[sl]);
                ae11[sl] = fmaf(W[10 - d], f2, ae11[sl]);
                ae22[sl] = fmaf(W[10 - d], f3, ae22[sl]);
                ae12[sl] = fmaf(W[10 - d], f4, ae12[sl]);
            }

            const int o = zb + s;
            if (o < D) {
                const float mu1 = am1[s], mu2 = am2[s];
                const float e11 = ae11[s], e22 = ae22[s], e12 = ae12[s];

                const float mu1s = mu1 * mu1;
                const float mu2s = mu2 * mu2;
                const float mu12 = mu1 * mu2;
                const float num = (2.f * mu12 + C1) * (2.f * (e12 - mu12) + C2);
                const float den = (mu1s + mu2s + C1) *
                                  ((e11 - mu1s) + (e22 - mu2s) + C2);
                lsum = fmaf(num, frcp(den), lsum);
            }
            am1[s] = am2[s] = ae11[s] = ae22[s] = ae12[s] = 0.f;
        }
    }

    // Block reduction (5 warps).
#pragma unroll
    for (int o = 16; o > 0; o >>= 1)
        lsum += __shfl_xor_sync(0xffffffffu, lsum, o);
    if ((tid & 31) == 0) red[tid >> 5] = lsum;
    __syncthreads();
    if (tid == 0) {
        float ssum = 0.f;
#pragma unroll
        for (int w = 0; w < 5; w++) ssum += red[w];
        atomicAdd(&g_sum, (double)ssum);
    }
}

__global__ void init_kernel() { g_sum = 0.0; }

__global__ void fin_kernel(float* __restrict__ out) {
    out[0] = (float)(g_sum / (double)NIMG);
}

extern "C" void kernel_launch(void* const* d_in, const int* in_sizes, int n_in,
                              void* d_out, int out_size) {
    const float* img1 = (const float*)d_in[0];
    const float* img2 = (const float*)d_in[1];
    (void)in_sizes; (void)n_in; (void)out_size;

    init_kernel<<<1, 1>>>();
    dim3 grid(160, 4);
    pass_a<<<grid, 160>>>(img1, img2);
    pass_b<<<grid, 160>>>();
    fin_kernel<<<1, 1>>>((float*)d_out);
}

// round 5
// speedup vs baseline: 1.3297x; 1.3297x over previous
#include <cuda_runtime.h>
#include <cuda_fp16.h>

// ---------------------------------------------------------------------------
// SSIM3D: two fp32 volumes (4,1,160,160,160), 11-tap separable Gaussian,
// 5 statistics (mu1, mu2, E11, E22, E12), scalar mean output.
//
// R5: R2's proven tiled 2-pass structure, with the instruction stream cut
// ~2x via packed f32x2 math (fma.rn.f32x2 / mul.rn.f32x2, sm_100+):
//  - pass_xy: input tile interleaved (a,c) float2 -> LDS.64; (m1,m2) and
//    (e11,e22) conv chains are FFMA2; e12 scalar FFMA-imm. Stage-3 y-conv
//    also FFMA2 on pair-interleaved smem planes.
//  - pass_z: pair over x from the fp16 intermediate (half2 -> f32x2),
//    z-conv all FFMA2, SSIM map with FMA-only Newton reciprocal.
// ---------------------------------------------------------------------------

typedef unsigned long long u64t;

namespace {
constexpr int D    = 160;
constexpr int DD   = D * D;                 // 25600
constexpr int NB   = 4;
constexpr long long VOL  = (long long)D * DD;       // 4,096,000
constexpr long long NIMG = (long long)NB * VOL;     // 16,384,000
constexpr int HALO = 5;
constexpr int RX = 42, RY = 42, RZ = 42;
constexpr int SXP = 43;   // u64 stride, interleaved input tile
constexpr int TSP = 33;   // u64 stride, tm/te planes; float stride for ts
constexpr int UZP = 17;   // u64 stride, pass_z tile (x-pairs)
constexpr float C1 = 0.0001f;   // 0.01^2
constexpr float C2 = 0.0009f;   // 0.03^2
}

// Normalized Gaussian, sigma=1.5, 11 taps.
__device__ constexpr float W[11] = {
    0.00102838f, 0.00759876f, 0.03600077f, 0.10936070f, 0.21300554f,
    0.26601173f,
    0.21300554f, 0.10936070f, 0.03600077f, 0.00759876f, 0.00102838f};

// 5 channels x 4 batches x 160^3 halfs = 163.84 MB scratch.
__device__ __half g_mid[5ll * 16384000ll];
__device__ double g_sum;

// ---- packed f32x2 helpers ----
__device__ __forceinline__ u64t pk(float x, float y) {
    u64t r; asm("mov.b64 %0, {%1, %2};" : "=l"(r) : "f"(x), "f"(y)); return r;
}
__device__ __forceinline__ float2 unpk(u64t v) {
    float2 f; asm("mov.b64 {%0, %1}, %2;" : "=f"(f.x), "=f"(f.y) : "l"(v));
    return f;
}
__device__ __forceinline__ u64t fma2(u64t a, u64t w, u64t d) {
    asm("fma.rn.f32x2 %0, %1, %2, %0;" : "+l"(d) : "l"(a), "l"(w));
    return d;
}
__device__ __forceinline__ u64t mul2(u64t a, u64t b) {
    u64t r; asm("mul.rn.f32x2 %0, %1, %2;" : "=l"(r) : "l"(a), "l"(b));
    return r;
}

// Pure-FMA reciprocal (den positive, >= ~9e-8); 3 Newton steps -> ~1ulp.
__device__ __forceinline__ float frcp(float x) {
    float r = __int_as_float(0x7EF311C3 - __float_as_int(x));
    r = r * (2.0f - x * r);
    r = r * (2.0f - x * r);
    r = r * (2.0f - x * r);
    return r;
}

__device__ __forceinline__ float ssim_pt(float mu1, float mu2, float e11,
                                         float e22, float e12) {
    const float mu1s = mu1 * mu1;
    const float mu2s = mu2 * mu2;
    const float mu12 = mu1 * mu2;
    const float num = (2.f * mu12 + C1) * (2.f * (e12 - mu12) + C2);
    const float den = (mu1s + mu2s + C1) * ((e11 - mu1s) + (e22 - mu2s) + C2);
    return num * frcp(den);
}

// ---------------------------------------------------------------------------
// Pass A: x-conv then y-conv for one z-slice tile (32x32 output).
// grid = (25 tiles, 160 z, 4 b), block = 384 threads.
// ---------------------------------------------------------------------------
__global__ void __launch_bounds__(384) pass_xy(const float* __restrict__ img1,
                                               const float* __restrict__ img2) {
    __shared__ u64t sAC[RY * SXP];    // interleaved (a,c) input tile
    __shared__ u64t tm[RY * TSP];     // (m1,m2) after x-conv
    __shared__ u64t te[RY * TSP];     // (e11,e22) after x-conv
    __shared__ float ts[RY * TSP];    // e12 after x-conv

    const int tile = blockIdx.x;            // 0..24
    const int x0 = (tile % 5) * 32;
    const int y0 = (tile / 5) * 32;
    const int z  = blockIdx.y;
    const int b  = blockIdx.z;
    const int tid = threadIdx.x;

    const float* p1 = img1 + (long long)b * VOL + (long long)z * DD;
    const float* p2 = img2 + (long long)b * VOL + (long long)z * DD;

    // Stage 1: load 42x42 halo region, interleaved (a,c) pairs.
    for (int l = tid; l < RY * RX; l += 384) {
        const int j = l / RX, i = l - j * RX;
        const int gy = y0 - HALO + j;
        const int gx = x0 - HALO + i;
        float a = 0.f, c = 0.f;
        if (gy >= 0 && gy < D && gx >= 0 && gx < D) {
            a = p1[gy * D + gx];
            c = p2[gy * D + gx];
        }
        sAC[j * SXP + i] = pk(a, c);
    }
    __syncthreads();

    u64t W2[11];
#pragma unroll
    for (int k = 0; k < 11; k++) W2[k] = pk(W[k], W[k]);

    // Stage 2: x-conv, 42 rows x 8 chunks of 4 outputs. 336 units.
    if (tid < 336) {
        const int row   = tid % 42;
        const int chunk = tid / 42;
        const int base = row * SXP + chunk * 4;
        u64t ac[14], sq[14];
        float p12[14];
#pragma unroll
        for (int j = 0; j < 14; j++) ac[j] = sAC[base + j];
#pragma unroll
        for (int j = 0; j < 14; j++) {
            sq[j] = mul2(ac[j], ac[j]);
            const float2 t = unpk(ac[j]);
            p12[j] = t.x * t.y;
        }
#pragma unroll
        for (int i = 0; i < 4; i++) {
            u64t am = 0ull, ae = 0ull;
            float a12 = 0.f;
#pragma unroll
            for (int k = 0; k < 11; k++) {
                am  = fma2(ac[i + k], W2[k], am);
                ae  = fma2(sq[i + k], W2[k], ae);
                a12 = fmaf(W[k], p12[i + k], a12);
            }
            const int x = chunk * 4 + i;
            tm[row * TSP + x] = am;
            te[row * TSP + x] = ae;
            ts[row * TSP + x] = a12;
        }
    }
    __syncthreads();

    // Stage 3: y-conv, write fp16 planes. 3 groups x 32 tx x 4 chunks = 384.
    {
        const int g = tid >> 7;              // 0: m-pair, 1: e-pair, 2: e12
        const int r = tid & 127;
        const int tx = r & 31;
        const int chunk = r >> 5;            // 0..3
        const long long cs = (long long)NB * VOL;
        __half* o0 = g_mid + (long long)b * VOL + (long long)z * DD + x0 + tx;

        if (g < 2) {
            const u64t* tp = (g == 0) ? tm : te;
            __half* q0 = o0 + (g == 0 ? 0 : 2 * cs);
            __half* q1 = q0 + cs;
            u64t v[18];
#pragma unroll
            for (int j = 0; j < 18; j++)
                v[j] = tp[(chunk * 8 + j) * TSP + tx];
#pragma unroll
            for (int i = 0; i < 8; i++) {
                u64t acc = 0ull;
#pragma unroll
                for (int k = 0; k < 11; k++) acc = fma2(v[i + k], W2[k], acc);
                const float2 f = unpk(acc);
                const long long yo = (long long)(y0 + chunk * 8 + i) * D;
                q0[yo] = __float2half_rn(f.x);
                q1[yo] = __float2half_rn(f.y);
            }
        } else {
            __half* q4 = o0 + 4 * cs;
            float v[18];
#pragma unroll
            for (int j = 0; j < 18; j++)
                v[j] = ts[(chunk * 8 + j) * TSP + tx];
#pragma unroll
            for (int i = 0; i < 8; i++) {
                float acc = 0.f;
#pragma unroll
                for (int k = 0; k < 11; k++) acc = fmaf(W[k], v[i + k], acc);
                q4[(long long)(y0 + chunk * 8 + i) * D] = __float2half_rn(acc);
            }
        }
    }
}

// ---------------------------------------------------------------------------
// Pass B: z-conv + SSIM map + reduction, paired over x.
// grid = (25 tiles [x,z], 160 y, 4 b), block = 128 threads.
// ---------------------------------------------------------------------------
__global__ void __launch_bounds__(128) pass_z() {
    __shared__ u64t u5[5 * RZ * UZP];
    __shared__ float red[4];

    const int tile = blockIdx.x;
    const int x0 = (tile % 5) * 32;
    const int z0 = (tile / 5) * 32;
    const int y  = blockIdx.y;
    const int b  = blockIdx.z;
    const int tid = threadIdx.x;

    const long long cs = (long long)NB * VOL;
    const __half* basep = g_mid + (long long)b * VOL + (long long)y * D + x0;

    // Fill: 5 channels x 42 z-rows x 16 x-pairs (zero pad in z).
    for (int l = tid; l < 5 * RZ * 16; l += 128) {
        const int ch = l / (RZ * 16);
        const int rem = l - ch * (RZ * 16);
        const int zz = rem >> 4;
        const int p  = rem & 15;
        const int gz = z0 - HALO + zz;
        float2 v = make_float2(0.f, 0.f);
        if (gz >= 0 && gz < D) {
            const __half2 h =
                *(const __half2*)(basep + ch * cs + (long long)gz * DD + 2 * p);
            v = __half22float2(h);
        }
        u5[(ch * RZ + zz) * UZP + p] = pk(v.x, v.y);
    }
    __syncthreads();

    u64t W2[11];
#pragma unroll
    for (int k = 0; k < 11; k++) W2[k] = pk(W[k], W[k]);

    // Each thread: one x-pair, 4 z-outputs.
    const int xp = tid & 15;
    const int zc = tid >> 4;            // 0..7
    u64t rr[5][4];
#pragma unroll
    for (int ch = 0; ch < 5; ch++) {
        u64t v[14];
#pragma unroll
        for (int j = 0; j < 14; j++)
            v[j] = u5[(ch * RZ + zc * 4 + j) * UZP + xp];
#pragma unroll
        for (int i = 0; i < 4; i++) {
            u64t acc = 0ull;
#pragma unroll
            for (int k = 0; k < 11; k++) acc = fma2(v[i + k], W2[k], acc);
            rr[ch][i] = acc;
        }
    }

    float lsum = 0.f;
#pragma unroll
    for (int i = 0; i < 4; i++) {
        const float2 m1  = unpk(rr[0][i]);
        const float2 m2  = unpk(rr[1][i]);
        const float2 e11 = unpk(rr[2][i]);
        const float2 e22 = unpk(rr[3][i]);
        const float2 e12 = unpk(rr[4][i]);
        lsum += ssim_pt(m1.x, m2.x, e11.x, e22.x, e12.x);
        lsum += ssim_pt(m1.y, m2.y, e11.y, e22.y, e12.y);
    }

    // Block reduction (4 warps).
#pragma unroll
    for (int o = 16; o > 0; o >>= 1)
        lsum += __shfl_xor_sync(0xffffffffu, lsum, o);
    if ((tid & 31) == 0) red[tid >> 5] = lsum;
    __syncthreads();
    if (tid == 0) {
        float s = 0.f;
#pragma unroll
        for (int w = 0; w < 4; w++) s += red[w];
        atomicAdd(&g_sum, (double)s);
    }
}

__global__ void init_kernel() { g_sum = 0.0; }

__global__ void fin_kernel(float* __restrict__ out) {
    out[0] = (float)(g_sum / (double)NIMG);
}

extern "C" void kernel_launch(void* const* d_in, const int* in_sizes, int n_in,
                              void* d_out, int out_size) {
    const float* img1 = (const float*)d_in[0];
    const float* img2 = (const float*)d_in[1];
    (void)in_sizes; (void)n_in; (void)out_size;

    init_kernel<<<1, 1>>>();
    dim3 grid(25, 160, 4);
    pass_xy<<<grid, 384>>>(img1, img2);
    pass_z<<<grid, 128>>>();
    fin_kernel<<<1, 1>>>((float*)d_out);
}